// round 13
// baseline (speedup 1.0000x reference)
#include <cuda_runtime.h>
#include <cuda_fp16.h>
#include <math.h>
#include <stdint.h>

// ---------------------------------------------------------------- constants
#define NROWS 32768          // B*L
#define EQ    1280
#define KDIM  1280
#define VQ    32
#define PQ    496
#define N2P   640            // padded width of second GEMM (528 -> 640)
#define LN_EPS 1e-12f
#define KC    32             // K per chunk (2 ks-steps of 16)
#define NCH   (KDIM / KC)    // 40
#define NSTG  3              // cp.async pipeline stages

// ---------------------------------------------------------------- scratch
__device__ __half g_hf[(size_t)NROWS * EQ];          // post-GELU hidden (fp16)
__device__ float g_l2[(size_t)NROWS * N2P];          // [pi_logits | Theta | pad]
__device__ __half g_xf[(size_t)NROWS * KDIM];        // hx fp16
__device__ __half g_af[(size_t)NROWS * KDIM];        // LN(h) fp16
__device__ __half g_w1f[(size_t)EQ * KDIM];          // dense_w^T fp16 [n][k]
__device__ __half g_w2f[(size_t)N2P * KDIM];         // packed [theta|Theta]^T fp16
__device__ float g_b2[N2P];

// ---------------------------------------------------------------- PTX utils
__device__ __forceinline__ uint32_t smem_u32(const void* p) {
    uint32_t a;
    asm("{ .reg .u64 t; cvta.to.shared.u64 t, %1; cvt.u32.u64 %0, t; }"
        : "=r"(a) : "l"(p));
    return a;
}
__device__ __forceinline__ void ldsm4(uint32_t* r, uint32_t addr) {
    asm volatile("ldmatrix.sync.aligned.m8n8.x4.shared.b16 {%0,%1,%2,%3}, [%4];"
                 : "=r"(r[0]), "=r"(r[1]), "=r"(r[2]), "=r"(r[3]) : "r"(addr));
}
__device__ __forceinline__ void mma16816(float* d, const uint32_t* a,
                                         const uint32_t* b) {
    asm volatile(
        "mma.sync.aligned.m16n8k16.row.col.f32.f16.f16.f32 "
        "{%0,%1,%2,%3}, {%4,%5,%6,%7}, {%8,%9}, {%0,%1,%2,%3};"
        : "+f"(d[0]), "+f"(d[1]), "+f"(d[2]), "+f"(d[3])
        : "r"(a[0]), "r"(a[1]), "r"(a[2]), "r"(a[3]), "r"(b[0]), "r"(b[1]));
}
__device__ __forceinline__ void cpasync16(uint32_t dst, const void* src) {
    asm volatile("cp.async.cg.shared.global [%0], [%1], 16;"
                 :: "r"(dst), "l"(src));
}
#define CP_COMMIT() asm volatile("cp.async.commit_group;" ::: "memory")
#define CP_WAIT1()  asm volatile("cp.async.wait_group 1;" ::: "memory")
#define CP_WAIT0()  asm volatile("cp.async.wait_group 0;" ::: "memory")

// ---------------------------------------------------------------- prep kernels
__global__ void conv_x_kernel(const float* __restrict__ x) {
    size_t idx = (size_t)blockIdx.x * blockDim.x + threadIdx.x;
    if (idx >= (size_t)NROWS * KDIM / 4) return;
    float4 v = ((const float4*)x)[idx];
    ushort4 hv = make_ushort4(__half_as_ushort(__float2half_rn(v.x)),
                              __half_as_ushort(__float2half_rn(v.y)),
                              __half_as_ushort(__float2half_rn(v.z)),
                              __half_as_ushort(__float2half_rn(v.w)));
    ((ushort4*)g_xf)[idx] = hv;
}

__global__ void conv_w1_kernel(const float* __restrict__ w) {
    int idx = blockIdx.x * blockDim.x + threadIdx.x;
    if (idx >= EQ * KDIM) return;
    int n = idx / KDIM;
    int k = idx - n * KDIM;
    g_w1f[idx] = __float2half_rn(w[(size_t)k * EQ + n]);
}

__global__ void conv_w2_kernel(const float* __restrict__ tw,
                               const float* __restrict__ tb,
                               const float* __restrict__ Tw,
                               const float* __restrict__ Tb) {
    int idx = blockIdx.x * blockDim.x + threadIdx.x;
    if (idx < N2P * KDIM) {
        int n = idx / KDIM;
        int k = idx - n * KDIM;
        float v = 0.0f;
        if (n < VQ)           v = tw[(size_t)k * VQ + n];
        else if (n < VQ + PQ) v = Tw[(size_t)k * PQ + (n - VQ)];
        g_w2f[idx] = __float2half_rn(v);
    }
    if (idx < N2P)
        g_b2[idx] = (idx < VQ) ? tb[idx] : (idx < VQ + PQ ? Tb[idx - VQ] : 0.0f);
}

// ---------------------------------------------------------------- GEMM (HMMA)
// C[64x128 tile] = A @ B^T, fp16 operands, fp32 accumulate, K-major.
// 128-thread CTAs, warp grid 2(m) x 2(n), warp tile 32x64 (2 m-frags x 8
// n-frags). 4 independent CTAs/SM: co-resident CTAs have unsynchronized
// phases, so one CTA's MMA burst overlaps another CTA's LDSM/cp.async phase.
// KC=32, NSTG=3, register-double-buffered fragments, 2 cp.async groups in
// flight (issue c+2 at top of iteration c; buffer safety from prior barrier).
// SMEM per stage: A 64x80B + B 128x80B = 15360B.
template <bool GELU, typename OutT>
__global__ void __launch_bounds__(128, 4)
gemm_mma_kernel(const __half* __restrict__ Af,
                const __half* __restrict__ Bf,
                const float* __restrict__ bias, OutT* __restrict__ C,
                int ldc) {
    extern __shared__ char sm[];
    const uint32_t sb = smem_u32(sm);
    constexpr uint32_t RS = 80;
    constexpr uint32_t APIECE = 64 * RS;          // 5120
    constexpr uint32_t BPIECE = 128 * RS;         // 10240
    constexpr uint32_t STAGE = APIECE + BPIECE;   // 15360

    int tid = threadIdx.x;
    int lane = tid & 31;
    int wid = tid >> 5;          // 0..3
    int wm = (wid & 1) * 32;     // warp m-offset within 64
    int wn = (wid >> 1) * 64;    // warp n-offset within 128
    int m0 = blockIdx.y * 64;
    int n0 = blockIdx.x * 128;

    // cp.async mapping:
    //   A: row = tid>>1 (0..63), 32B half chosen by tid&1  -> 2 x 16B
    //   B: row = tid (0..127), full 64B row                -> 4 x 16B
    int ar = tid >> 1;
    int ah_ = (tid & 1);
    const __half* pA = Af + (size_t)(m0 + ar) * KDIM + ah_ * 16;
    const __half* pB = Bf + (size_t)(n0 + tid) * KDIM;
    uint32_t aOff = (uint32_t)ar * RS + (uint32_t)ah_ * 32;
    uint32_t bOff = APIECE + (uint32_t)tid * RS;

    auto issue = [&](int c) {
        uint32_t d = sb + (uint32_t)(c % NSTG) * STAGE;
        size_t g = (size_t)c * KC;
        cpasync16(d + aOff,      pA + g);
        cpasync16(d + aOff + 16, pA + g + 8);
        cpasync16(d + bOff,      pB + g);
        cpasync16(d + bOff + 16, pB + g + 8);
        cpasync16(d + bOff + 32, pB + g + 16);
        cpasync16(d + bOff + 48, pB + g + 24);
        CP_COMMIT();
    };

    // ldmatrix per-lane offsets
    int rA = (lane & 7) + ((lane >> 3) & 1) * 8;
    uint32_t kA = (uint32_t)((lane >> 4) & 1) * 16;
    int rB = (lane & 7) + ((lane >> 4) & 1) * 8;
    uint32_t kB = (uint32_t)((lane >> 3) & 1) * 16;

    auto ldfrag = [&](uint32_t st, uint32_t kbyte, uint32_t (*ah)[4],
                      uint32_t (*bh)[2]) {
#pragma unroll
        for (int mf = 0; mf < 2; mf++)
            ldsm4(ah[mf], st + (uint32_t)(wm + mf * 16 + rA) * RS + kbyte + kA);
#pragma unroll
        for (int g = 0; g < 4; g++) {
            uint32_t t[4];
            ldsm4(t, st + APIECE +
                         (uint32_t)(wn + g * 16 + rB) * RS + kbyte + kB);
            bh[2 * g][0] = t[0]; bh[2 * g][1] = t[1];
            bh[2 * g + 1][0] = t[2]; bh[2 * g + 1][1] = t[3];
        }
    };

    float acc[2][8][4];
#pragma unroll
    for (int i = 0; i < 2; i++)
#pragma unroll
        for (int j = 0; j < 8; j++)
#pragma unroll
            for (int q = 0; q < 4; q++) acc[i][j][q] = 0.0f;

    uint32_t a0[2][4], b0[8][2];   // fragment ping (ks even)
    uint32_t a1[2][4], b1[8][2];   // fragment pong (ks odd)

#define MMA_ALL(A, B)                                                         \
    _Pragma("unroll") for (int mf = 0; mf < 2; mf++)                          \
        _Pragma("unroll") for (int nf = 0; nf < 8; nf++)                      \
            mma16816(acc[mf][nf], (A)[mf], (B)[nf]);

    issue(0);
    issue(1);
    CP_WAIT1();          // chunk 0 landed
    __syncthreads();
    ldfrag(sb, 0, a0, b0);

    for (int c = 0; c < NCH; c++) {
        // issue chunk c+2 into buffer (c+2)%3: its previous tenant (chunk
        // c-1) had its last readers before the barrier of iteration c-1.
        if (c + 2 < NCH) issue(c + 2);

        uint32_t st = sb + (uint32_t)(c % NSTG) * STAGE;
        // load ks1 fragments of chunk c; MMA ks0 hides the latency
        ldfrag(st, 32, a1, b1);
        MMA_ALL(a0, b0);

        if (c + 1 < NCH) {
            if (c + 2 < NCH) CP_WAIT1(); else CP_WAIT0();  // chunk c+1 landed
            __syncthreads();     // publish chunk c+1 to all warps
            ldfrag(sb + (uint32_t)((c + 1) % NSTG) * STAGE, 0, a0, b0);
        }
        MMA_ALL(a1, b1);
    }
#undef MMA_ALL

    // epilogue: bias (+ GELU); OutT = __half (GEMM1) or float (GEMM2)
    int tr = lane >> 2;
    int tc = (lane & 3) * 2;
#pragma unroll
    for (int mf = 0; mf < 2; mf++) {
#pragma unroll
        for (int nf = 0; nf < 8; nf++) {
            int col = n0 + wn + nf * 8 + tc;
            float2 bb = *(const float2*)&bias[col];
            int r1 = m0 + wm + mf * 16 + tr;
#pragma unroll
            for (int h = 0; h < 2; h++) {
                float v0 = acc[mf][nf][2 * h + 0] + bb.x;
                float v1 = acc[mf][nf][2 * h + 1] + bb.y;
                if (GELU) {
                    v0 = 0.5f * v0 * (1.0f + erff(v0 * 0.70710678118654752f));
                    v1 = 0.5f * v1 * (1.0f + erff(v1 * 0.70710678118654752f));
                }
                if constexpr (sizeof(OutT) == 2) {
                    __half2 hv = __floats2half2_rn(v0, v1);
                    *(__half2*)&C[(size_t)(r1 + 8 * h) * ldc + col] = hv;
                } else {
                    *(float2*)&C[(size_t)(r1 + 8 * h) * ldc + col] =
                        make_float2(v0, v1);
                }
            }
        }
    }
}

// ---------------------------------------------------------------- LayerNorm
__device__ __forceinline__ float block_reduce_sum(float v) {
    __shared__ float sh[8];
#pragma unroll
    for (int o = 16; o > 0; o >>= 1) v += __shfl_xor_sync(0xffffffffu, v, o);
    int lane = threadIdx.x & 31, wid = threadIdx.x >> 5;
    if (lane == 0) sh[wid] = v;
    __syncthreads();
    v = (lane < 8) ? sh[lane] : 0.0f;
#pragma unroll
    for (int o = 4; o > 0; o >>= 1) v += __shfl_xor_sync(0xffffffffu, v, o);
    v = __shfl_sync(0xffffffffu, v, 0);
    __syncthreads();
    return v;
}

// LN reads fp16 h, computes stats in fp32, writes fp16.
__global__ void ln_kernel(const __half* __restrict__ h,
                          const float* __restrict__ g,
                          const float* __restrict__ b) {
    size_t r = blockIdx.x;
    const __half* row = h + r * EQ;
    int t = threadIdx.x;
    float x[5];
    float s = 0.0f;
#pragma unroll
    for (int i = 0; i < 5; i++) {
        x[i] = __half2float(row[t + i * 256]);
        s += x[i];
    }
    float mu = block_reduce_sum(s) * (1.0f / EQ);
    float v = 0.0f;
#pragma unroll
    for (int i = 0; i < 5; i++) { float d = x[i] - mu; v += d * d; }
    float var = block_reduce_sum(v) * (1.0f / EQ);
    float inv = rsqrtf(var + LN_EPS);
#pragma unroll
    for (int i = 0; i < 5; i++) {
        int c = t + i * 256;
        float y = (x[i] - mu) * inv * g[c] + b[c];
        g_af[r * EQ + c] = __float2half_rn(y);
    }
}

// ---------------------------------------------------------------- finalize
__global__ void __launch_bounds__(256)
finalize_kernel(const int* __restrict__ mask32,
                float* __restrict__ qOut, float* __restrict__ piOut) {
    __shared__ float th[8][512];
    __shared__ float psq[8][32];
    __shared__ float mf[32];

    int lane = threadIdx.x;
    int w = threadIdx.y;
    size_t r = (size_t)blockIdx.x * 8 + w;

    if (w == 0) mf[lane] = (mask32[lane] != 0) ? 1.0f : 0.0f;
    __syncthreads();

    const float* base = g_l2 + r * N2P;

    bool mk = mf[lane] > 0.5f;
    float x = base[lane];
    float xm = mk ? x : -INFINITY;
    float mx = xm;
#pragma unroll
    for (int o = 16; o > 0; o >>= 1)
        mx = fmaxf(mx, __shfl_xor_sync(0xffffffffu, mx, o));
    float e = mk ? expf(xm - mx) : 0.0f;
    float ssum = e;
#pragma unroll
    for (int o = 16; o > 0; o >>= 1)
        ssum += __shfl_xor_sync(0xffffffffu, ssum, o);

    if (piOut) piOut[r * VQ + lane] = e / ssum;
    float logpi = xm - mx - logf(ssum);
    psq[w][lane] = mk ? expf(0.5f * logpi) : 1.0f;

    for (int idx = lane; idx < PQ; idx += 32) {
        float t = base[VQ + idx];
        th[w][idx] = fmaxf(t, 0.0f) + log1pf(expf(-fabsf(t)));
    }
    __syncwarp();

    int i = lane;
    float mi = mf[i];
    float inv = 1.0f / psq[w][i];
    float q[32];
    float rs = 0.0f;
#pragma unroll
    for (int j = 0; j < 32; j++) {
        float val = 0.0f;
        if (j != i) {
            int lo = min(i, j), hi = max(i, j);
            int idx = lo * VQ - (lo * (lo + 1)) / 2 + (hi - lo - 1);
            val = th[w][idx] * mi * mf[j] * psq[w][j] * inv;
        }
        q[j] = val;
        rs += val;
    }
#pragma unroll
    for (int j = 0; j < 32; j++)
        if (j == i) q[j] = -rs;

    float* out = qOut + r * (VQ * VQ) + (size_t)i * VQ;
#pragma unroll
    for (int j = 0; j < 32; j += 4)
        *(float4*)(out + j) = make_float4(q[j], q[j + 1], q[j + 2], q[j + 3]);
}

// ---------------------------------------------------------------- launch
extern "C" void kernel_launch(void* const* d_in, const int* in_sizes, int n_in,
                              void* d_out, int out_size) {
    const float* hx      = (const float*)d_in[0];
    const int*   vmask   = (const int*)d_in[1];
    const float* dense_w = (const float*)d_in[2];
    const float* dense_b = (const float*)d_in[3];
    const float* ln_g    = (const float*)d_in[4];
    const float* ln_b    = (const float*)d_in[5];
    const float* theta_w = (const float*)d_in[6];
    const float* theta_b = (const float*)d_in[7];
    const float* Theta_w = (const float*)d_in[8];
    const float* Theta_b = (const float*)d_in[9];

    float *l2ptr, *b2ptr;
    __half *hfp, *xf, *af, *w1f, *w2f;
    cudaGetSymbolAddress((void**)&hfp, g_hf);
    cudaGetSymbolAddress((void**)&l2ptr, g_l2);
    cudaGetSymbolAddress((void**)&b2ptr, g_b2);
    cudaGetSymbolAddress((void**)&xf, g_xf);
    cudaGetSymbolAddress((void**)&af, g_af);
    cudaGetSymbolAddress((void**)&w1f, g_w1f);
    cudaGetSymbolAddress((void**)&w2f, g_w2f);

    const size_t Q_ELEMS = (size_t)NROWS * VQ * VQ;
    const size_t PI_ELEMS = (size_t)NROWS * VQ;
    float* qOut = (float*)d_out;
    float* piOut = ((size_t)out_size >= Q_ELEMS + PI_ELEMS) ? (qOut + Q_ELEMS)
                                                            : nullptr;

    const int SMEM = NSTG * (64 + 128) * 80;   // 46080 bytes -> 4 CTAs/SM
    cudaFuncSetAttribute(gemm_mma_kernel<true, __half>,
                         cudaFuncAttributeMaxDynamicSharedMemorySize, SMEM);
    cudaFuncSetAttribute(gemm_mma_kernel<false, float>,
                         cudaFuncAttributeMaxDynamicSharedMemorySize, SMEM);

    // 1. prep: convert activations/weights to fp16 (weights K-major)
    conv_x_kernel<<<(NROWS * KDIM / 4 + 255) / 256, 256>>>(hx);
    conv_w1_kernel<<<(EQ * KDIM + 255) / 256, 256>>>(dense_w);
    conv_w2_kernel<<<(N2P * KDIM + 255) / 256, 256>>>(theta_w, theta_b,
                                                      Theta_w, Theta_b);

    // 2. h = gelu(hx @ dense_w + dense_b) -> fp16   [M=32768, N=1280, K=1280]
    {
        dim3 grid(EQ / 128, NROWS / 64);
        gemm_mma_kernel<true, __half><<<grid, 128, SMEM>>>(xf, w1f, dense_b,
                                                           hfp, EQ);
    }

    // 3. LayerNorm (fp16 in/out, fp32 stats)
    ln_kernel<<<NROWS, 256>>>(hfp, ln_g, ln_b);

    // 4. logits2 = LN(h) @ [theta|Theta] + bias  [M=32768, N=640, K=1280]
    {
        dim3 grid(N2P / 128, NROWS / 64);
        gemm_mma_kernel<false, float><<<grid, 128, SMEM>>>(af, w2f, b2ptr,
                                                           l2ptr, N2P);
    }

    // 5. per-row epilogue -> Q, pi
    finalize_kernel<<<NROWS / 8, dim3(32, 8)>>>(vmask, qOut, piOut);
}

// round 14
// speedup vs baseline: 1.1186x; 1.1186x over previous
#include <cuda_runtime.h>
#include <cuda_fp16.h>
#include <math.h>
#include <stdint.h>

// ---------------------------------------------------------------- constants
#define NROWS 32768          // B*L
#define EQ    1280
#define KDIM  1280
#define VQ    32
#define PQ    496
#define N2P   640            // padded width of second GEMM (528 -> 640)
#define LN_EPS 1e-12f
#define KC    32             // K per chunk (2 ks-steps of 16)
#define NCH   (KDIM / KC)    // 40
#define NSTG  3              // cp.async pipeline stages

// ---------------------------------------------------------------- scratch
__device__ __half g_hf[(size_t)NROWS * EQ];          // post-GELU hidden (fp16)
__device__ float g_l2[(size_t)NROWS * N2P];          // [pi_logits | Theta | pad]
__device__ __half g_xf[(size_t)NROWS * KDIM];        // hx fp16
__device__ __half g_af[(size_t)NROWS * KDIM];        // LN(h) fp16
__device__ __half g_w1f[(size_t)EQ * KDIM];          // dense_w^T fp16 [n][k]
__device__ __half g_w2f[(size_t)N2P * KDIM];         // packed [theta|Theta]^T fp16
__device__ float g_b2[N2P];

// ---------------------------------------------------------------- PTX utils
__device__ __forceinline__ uint32_t smem_u32(const void* p) {
    uint32_t a;
    asm("{ .reg .u64 t; cvta.to.shared.u64 t, %1; cvt.u32.u64 %0, t; }"
        : "=r"(a) : "l"(p));
    return a;
}
__device__ __forceinline__ void ldsm4(uint32_t* r, uint32_t addr) {
    asm volatile("ldmatrix.sync.aligned.m8n8.x4.shared.b16 {%0,%1,%2,%3}, [%4];"
                 : "=r"(r[0]), "=r"(r[1]), "=r"(r[2]), "=r"(r[3]) : "r"(addr));
}
__device__ __forceinline__ void mma16816(float* d, const uint32_t* a,
                                         const uint32_t* b) {
    asm volatile(
        "mma.sync.aligned.m16n8k16.row.col.f32.f16.f16.f32 "
        "{%0,%1,%2,%3}, {%4,%5,%6,%7}, {%8,%9}, {%0,%1,%2,%3};"
        : "+f"(d[0]), "+f"(d[1]), "+f"(d[2]), "+f"(d[3])
        : "r"(a[0]), "r"(a[1]), "r"(a[2]), "r"(a[3]), "r"(b[0]), "r"(b[1]));
}
__device__ __forceinline__ void cpasync16(uint32_t dst, const void* src) {
    asm volatile("cp.async.cg.shared.global [%0], [%1], 16;"
                 :: "r"(dst), "l"(src));
}
#define CP_COMMIT() asm volatile("cp.async.commit_group;" ::: "memory")
#define CP_WAIT1()  asm volatile("cp.async.wait_group 1;" ::: "memory")
#define CP_WAIT0()  asm volatile("cp.async.wait_group 0;" ::: "memory")

// ---------------------------------------------------------------- prep kernels
__global__ void conv_x_kernel(const float* __restrict__ x) {
    size_t idx = (size_t)blockIdx.x * blockDim.x + threadIdx.x;
    if (idx >= (size_t)NROWS * KDIM / 4) return;
    float4 v = ((const float4*)x)[idx];
    ushort4 hv = make_ushort4(__half_as_ushort(__float2half_rn(v.x)),
                              __half_as_ushort(__float2half_rn(v.y)),
                              __half_as_ushort(__float2half_rn(v.z)),
                              __half_as_ushort(__float2half_rn(v.w)));
    ((ushort4*)g_xf)[idx] = hv;
}

__global__ void conv_w1_kernel(const float* __restrict__ w) {
    int idx = blockIdx.x * blockDim.x + threadIdx.x;
    if (idx >= EQ * KDIM) return;
    int n = idx / KDIM;
    int k = idx - n * KDIM;
    g_w1f[idx] = __float2half_rn(w[(size_t)k * EQ + n]);
}

__global__ void conv_w2_kernel(const float* __restrict__ tw,
                               const float* __restrict__ tb,
                               const float* __restrict__ Tw,
                               const float* __restrict__ Tb) {
    int idx = blockIdx.x * blockDim.x + threadIdx.x;
    if (idx < N2P * KDIM) {
        int n = idx / KDIM;
        int k = idx - n * KDIM;
        float v = 0.0f;
        if (n < VQ)           v = tw[(size_t)k * VQ + n];
        else if (n < VQ + PQ) v = Tw[(size_t)k * PQ + (n - VQ)];
        g_w2f[idx] = __float2half_rn(v);
    }
    if (idx < N2P)
        g_b2[idx] = (idx < VQ) ? tb[idx] : (idx < VQ + PQ ? Tb[idx - VQ] : 0.0f);
}

// ---------------------------------------------------------------- GEMM (HMMA)
// C[128x128] = A @ B^T, fp16 operands, fp32 accumulate, K-major.
// 128-thread CTA, warp grid 2(m) x 2(n), FAT warp tile 64x64:
// smem traffic per MMA drops from 192B (32x64) to 128B (64x64).
// KC=32, NSTG=3, single barrier per chunk, fragment ping-pong.
// 2 CTAs/SM (255 regs x 128 thr x 2 = full RF; smem 61.4KB x 2).
// SMEM per stage: A 128x80B + B 128x80B = 20480B.
template <bool GELU, typename OutT>
__global__ void __launch_bounds__(128, 2)
gemm_mma_kernel(const __half* __restrict__ Af,
                const __half* __restrict__ Bf,
                const float* __restrict__ bias, OutT* __restrict__ C,
                int ldc) {
    extern __shared__ char sm[];
    const uint32_t sb = smem_u32(sm);
    constexpr uint32_t RS = 80;
    constexpr uint32_t PIECE = 128 * RS;          // 10240
    constexpr uint32_t STAGE = 2 * PIECE;         // 20480

    int tid = threadIdx.x;
    int lane = tid & 31;
    int wid = tid >> 5;          // 0..3
    int wm = (wid & 1) * 64;     // warp m-offset
    int wn = (wid >> 1) * 64;    // warp n-offset
    int m0 = blockIdx.y * 128;
    int n0 = blockIdx.x * 128;

    // cp.async mapping: thread owns one full 64B row of A and one of B
    const __half* pA = Af + (size_t)(m0 + tid) * KDIM;
    const __half* pB = Bf + (size_t)(n0 + tid) * KDIM;
    uint32_t aOff = (uint32_t)tid * RS;
    uint32_t bOff = PIECE + (uint32_t)tid * RS;

    auto issue = [&](int c) {
        uint32_t d = sb + (uint32_t)(c % NSTG) * STAGE;
        size_t g = (size_t)c * KC;
        cpasync16(d + aOff,      pA + g);
        cpasync16(d + aOff + 16, pA + g + 8);
        cpasync16(d + aOff + 32, pA + g + 16);
        cpasync16(d + aOff + 48, pA + g + 24);
        cpasync16(d + bOff,      pB + g);
        cpasync16(d + bOff + 16, pB + g + 8);
        cpasync16(d + bOff + 32, pB + g + 16);
        cpasync16(d + bOff + 48, pB + g + 24);
        CP_COMMIT();
    };

    // ldmatrix per-lane offsets
    int rA = (lane & 7) + ((lane >> 3) & 1) * 8;
    uint32_t kA = (uint32_t)((lane >> 4) & 1) * 16;
    int rB = (lane & 7) + ((lane >> 4) & 1) * 8;
    uint32_t kB = (uint32_t)((lane >> 3) & 1) * 16;

    auto ldfrag = [&](uint32_t st, uint32_t kbyte, uint32_t (*ah)[4],
                      uint32_t (*bh)[2]) {
#pragma unroll
        for (int mf = 0; mf < 4; mf++)
            ldsm4(ah[mf], st + (uint32_t)(wm + mf * 16 + rA) * RS + kbyte + kA);
#pragma unroll
        for (int g = 0; g < 4; g++) {
            uint32_t t[4];
            ldsm4(t, st + PIECE +
                         (uint32_t)(wn + g * 16 + rB) * RS + kbyte + kB);
            bh[2 * g][0] = t[0]; bh[2 * g][1] = t[1];
            bh[2 * g + 1][0] = t[2]; bh[2 * g + 1][1] = t[3];
        }
    };

    float acc[4][8][4];
#pragma unroll
    for (int i = 0; i < 4; i++)
#pragma unroll
        for (int j = 0; j < 8; j++)
#pragma unroll
            for (int q = 0; q < 4; q++) acc[i][j][q] = 0.0f;

    uint32_t a0[4][4], b0[8][2];   // fragment ping (ks even)
    uint32_t a1[4][4], b1[8][2];   // fragment pong (ks odd)

#define MMA_ALL(A, B)                                                         \
    _Pragma("unroll") for (int mf = 0; mf < 4; mf++)                          \
        _Pragma("unroll") for (int nf = 0; nf < 8; nf++)                      \
            mma16816(acc[mf][nf], (A)[mf], (B)[nf]);

    issue(0);
    issue(1);
    CP_WAIT1();          // chunk 0 landed
    __syncthreads();
    ldfrag(sb, 0, a0, b0);

    for (int c = 0; c < NCH; c++) {
        // issue chunk c+2 into buffer (c+2)%3 (safe: prior barrier retired it)
        if (c + 2 < NCH) issue(c + 2);

        uint32_t st = sb + (uint32_t)(c % NSTG) * STAGE;
        // load ks1 fragments of chunk c; MMA ks0 hides the latency
        ldfrag(st, 32, a1, b1);
        MMA_ALL(a0, b0);

        if (c + 1 < NCH) {
            if (c + 2 < NCH) CP_WAIT1(); else CP_WAIT0();  // chunk c+1 landed
            __syncthreads();     // publish chunk c+1 to all warps
            ldfrag(sb + (uint32_t)((c + 1) % NSTG) * STAGE, 0, a0, b0);
        }
        MMA_ALL(a1, b1);
    }
#undef MMA_ALL

    // epilogue: bias (+ GELU); OutT = __half (GEMM1) or float (GEMM2)
    int tr = lane >> 2;
    int tc = (lane & 3) * 2;
#pragma unroll
    for (int mf = 0; mf < 4; mf++) {
#pragma unroll
        for (int nf = 0; nf < 8; nf++) {
            int col = n0 + wn + nf * 8 + tc;
            float2 bb = *(const float2*)&bias[col];
            int r1 = m0 + wm + mf * 16 + tr;
#pragma unroll
            for (int h = 0; h < 2; h++) {
                float v0 = acc[mf][nf][2 * h + 0] + bb.x;
                float v1 = acc[mf][nf][2 * h + 1] + bb.y;
                if (GELU) {
                    v0 = 0.5f * v0 * (1.0f + erff(v0 * 0.70710678118654752f));
                    v1 = 0.5f * v1 * (1.0f + erff(v1 * 0.70710678118654752f));
                }
                if constexpr (sizeof(OutT) == 2) {
                    __half2 hv = __floats2half2_rn(v0, v1);
                    *(__half2*)&C[(size_t)(r1 + 8 * h) * ldc + col] = hv;
                } else {
                    *(float2*)&C[(size_t)(r1 + 8 * h) * ldc + col] =
                        make_float2(v0, v1);
                }
            }
        }
    }
}

// ---------------------------------------------------------------- LayerNorm
__device__ __forceinline__ float block_reduce_sum(float v) {
    __shared__ float sh[8];
#pragma unroll
    for (int o = 16; o > 0; o >>= 1) v += __shfl_xor_sync(0xffffffffu, v, o);
    int lane = threadIdx.x & 31, wid = threadIdx.x >> 5;
    if (lane == 0) sh[wid] = v;
    __syncthreads();
    v = (lane < 8) ? sh[lane] : 0.0f;
#pragma unroll
    for (int o = 4; o > 0; o >>= 1) v += __shfl_xor_sync(0xffffffffu, v, o);
    v = __shfl_sync(0xffffffffu, v, 0);
    __syncthreads();
    return v;
}

// LN reads fp16 h, computes stats in fp32, writes fp16.
__global__ void ln_kernel(const __half* __restrict__ h,
                          const float* __restrict__ g,
                          const float* __restrict__ b) {
    size_t r = blockIdx.x;
    const __half* row = h + r * EQ;
    int t = threadIdx.x;
    float x[5];
    float s = 0.0f;
#pragma unroll
    for (int i = 0; i < 5; i++) {
        x[i] = __half2float(row[t + i * 256]);
        s += x[i];
    }
    float mu = block_reduce_sum(s) * (1.0f / EQ);
    float v = 0.0f;
#pragma unroll
    for (int i = 0; i < 5; i++) { float d = x[i] - mu; v += d * d; }
    float var = block_reduce_sum(v) * (1.0f / EQ);
    float inv = rsqrtf(var + LN_EPS);
#pragma unroll
    for (int i = 0; i < 5; i++) {
        int c = t + i * 256;
        float y = (x[i] - mu) * inv * g[c] + b[c];
        g_af[r * EQ + c] = __float2half_rn(y);
    }
}

// ---------------------------------------------------------------- finalize
__global__ void __launch_bounds__(256)
finalize_kernel(const int* __restrict__ mask32,
                float* __restrict__ qOut, float* __restrict__ piOut) {
    __shared__ float th[8][512];
    __shared__ float psq[8][32];
    __shared__ float mf[32];

    int lane = threadIdx.x;
    int w = threadIdx.y;
    size_t r = (size_t)blockIdx.x * 8 + w;

    if (w == 0) mf[lane] = (mask32[lane] != 0) ? 1.0f : 0.0f;
    __syncthreads();

    const float* base = g_l2 + r * N2P;

    bool mk = mf[lane] > 0.5f;
    float x = base[lane];
    float xm = mk ? x : -INFINITY;
    float mx = xm;
#pragma unroll
    for (int o = 16; o > 0; o >>= 1)
        mx = fmaxf(mx, __shfl_xor_sync(0xffffffffu, mx, o));
    float e = mk ? expf(xm - mx) : 0.0f;
    float ssum = e;
#pragma unroll
    for (int o = 16; o > 0; o >>= 1)
        ssum += __shfl_xor_sync(0xffffffffu, ssum, o);

    if (piOut) piOut[r * VQ + lane] = e / ssum;
    float logpi = xm - mx - logf(ssum);
    psq[w][lane] = mk ? expf(0.5f * logpi) : 1.0f;

    for (int idx = lane; idx < PQ; idx += 32) {
        float t = base[VQ + idx];
        th[w][idx] = fmaxf(t, 0.0f) + log1pf(expf(-fabsf(t)));
    }
    __syncwarp();

    int i = lane;
    float mi = mf[i];
    float inv = 1.0f / psq[w][i];
    float q[32];
    float rs = 0.0f;
#pragma unroll
    for (int j = 0; j < 32; j++) {
        float val = 0.0f;
        if (j != i) {
            int lo = min(i, j), hi = max(i, j);
            int idx = lo * VQ - (lo * (lo + 1)) / 2 + (hi - lo - 1);
            val = th[w][idx] * mi * mf[j] * psq[w][j] * inv;
        }
        q[j] = val;
        rs += val;
    }
#pragma unroll
    for (int j = 0; j < 32; j++)
        if (j == i) q[j] = -rs;

    float* out = qOut + r * (VQ * VQ) + (size_t)i * VQ;
#pragma unroll
    for (int j = 0; j < 32; j += 4)
        *(float4*)(out + j) = make_float4(q[j], q[j + 1], q[j + 2], q[j + 3]);
}

// ---------------------------------------------------------------- launch
extern "C" void kernel_launch(void* const* d_in, const int* in_sizes, int n_in,
                              void* d_out, int out_size) {
    const float* hx      = (const float*)d_in[0];
    const int*   vmask   = (const int*)d_in[1];
    const float* dense_w = (const float*)d_in[2];
    const float* dense_b = (const float*)d_in[3];
    const float* ln_g    = (const float*)d_in[4];
    const float* ln_b    = (const float*)d_in[5];
    const float* theta_w = (const float*)d_in[6];
    const float* theta_b = (const float*)d_in[7];
    const float* Theta_w = (const float*)d_in[8];
    const float* Theta_b = (const float*)d_in[9];

    float *l2ptr, *b2ptr;
    __half *hfp, *xf, *af, *w1f, *w2f;
    cudaGetSymbolAddress((void**)&hfp, g_hf);
    cudaGetSymbolAddress((void**)&l2ptr, g_l2);
    cudaGetSymbolAddress((void**)&b2ptr, g_b2);
    cudaGetSymbolAddress((void**)&xf, g_xf);
    cudaGetSymbolAddress((void**)&af, g_af);
    cudaGetSymbolAddress((void**)&w1f, g_w1f);
    cudaGetSymbolAddress((void**)&w2f, g_w2f);

    const size_t Q_ELEMS = (size_t)NROWS * VQ * VQ;
    const size_t PI_ELEMS = (size_t)NROWS * VQ;
    float* qOut = (float*)d_out;
    float* piOut = ((size_t)out_size >= Q_ELEMS + PI_ELEMS) ? (qOut + Q_ELEMS)
                                                            : nullptr;

    const int SMEM = NSTG * 2 * 128 * 80;   // 61440 bytes -> 2 CTAs/SM
    cudaFuncSetAttribute(gemm_mma_kernel<true, __half>,
                         cudaFuncAttributeMaxDynamicSharedMemorySize, SMEM);
    cudaFuncSetAttribute(gemm_mma_kernel<false, float>,
                         cudaFuncAttributeMaxDynamicSharedMemorySize, SMEM);

    // 1. prep: convert activations/weights to fp16 (weights K-major)
    conv_x_kernel<<<(NROWS * KDIM / 4 + 255) / 256, 256>>>(hx);
    conv_w1_kernel<<<(EQ * KDIM + 255) / 256, 256>>>(dense_w);
    conv_w2_kernel<<<(N2P * KDIM + 255) / 256, 256>>>(theta_w, theta_b,
                                                      Theta_w, Theta_b);

    // 2. h = gelu(hx @ dense_w + dense_b) -> fp16   [M=32768, N=1280, K=1280]
    {
        dim3 grid(EQ / 128, NROWS / 128);
        gemm_mma_kernel<true, __half><<<grid, 128, SMEM>>>(xf, w1f, dense_b,
                                                           hfp, EQ);
    }

    // 3. LayerNorm (fp16 in/out, fp32 stats)
    ln_kernel<<<NROWS, 256>>>(hfp, ln_g, ln_b);

    // 4. logits2 = LN(h) @ [theta|Theta] + bias  [M=32768, N=640, K=1280]
    {
        dim3 grid(N2P / 128, NROWS / 128);
        gemm_mma_kernel<false, float><<<grid, 128, SMEM>>>(af, w2f, b2ptr,
                                                           l2ptr, N2P);
    }

    // 5. per-row epilogue -> Q, pi
    finalize_kernel<<<NROWS / 8, dim3(32, 8)>>>(vmask, qOut, piOut);
}

// round 15
// speedup vs baseline: 1.3156x; 1.1761x over previous
#include <cuda_runtime.h>
#include <cuda_fp16.h>
#include <math.h>
#include <stdint.h>

// ---------------------------------------------------------------- constants
#define NROWS 32768          // B*L
#define EQ    1280
#define KDIM  1280
#define VQ    32
#define PQ    496
#define N2P   640            // padded width of second GEMM (528 -> 640)
#define LN_EPS 1e-12f
#define KC    32             // K per chunk (2 ks-steps of 16)
#define NCH   (KDIM / KC)    // 40
#define NSTG  4              // cp.async pipeline stages

// ---------------------------------------------------------------- scratch
__device__ __half g_hf[(size_t)NROWS * EQ];          // post-GELU hidden (fp16)
__device__ float g_l2[(size_t)NROWS * N2P];          // [pi_logits | Theta | pad]
__device__ __half g_xf[(size_t)NROWS * KDIM];        // hx fp16
__device__ __half g_af[(size_t)NROWS * KDIM];        // LN(h) fp16
__device__ __half g_w1f[(size_t)EQ * KDIM];          // dense_w^T fp16 [n][k]
__device__ __half g_w2f[(size_t)N2P * KDIM];         // packed [theta|Theta]^T fp16
__device__ float g_b2[N2P];

// ---------------------------------------------------------------- PTX utils
__device__ __forceinline__ uint32_t smem_u32(const void* p) {
    uint32_t a;
    asm("{ .reg .u64 t; cvta.to.shared.u64 t, %1; cvt.u32.u64 %0, t; }"
        : "=r"(a) : "l"(p));
    return a;
}
__device__ __forceinline__ void ldsm4(uint32_t* r, uint32_t addr) {
    asm volatile("ldmatrix.sync.aligned.m8n8.x4.shared.b16 {%0,%1,%2,%3}, [%4];"
                 : "=r"(r[0]), "=r"(r[1]), "=r"(r[2]), "=r"(r[3]) : "r"(addr));
}
__device__ __forceinline__ void mma16816(float* d, const uint32_t* a,
                                         const uint32_t* b) {
    asm volatile(
        "mma.sync.aligned.m16n8k16.row.col.f32.f16.f16.f32 "
        "{%0,%1,%2,%3}, {%4,%5,%6,%7}, {%8,%9}, {%0,%1,%2,%3};"
        : "+f"(d[0]), "+f"(d[1]), "+f"(d[2]), "+f"(d[3])
        : "r"(a[0]), "r"(a[1]), "r"(a[2]), "r"(a[3]), "r"(b[0]), "r"(b[1]));
}
__device__ __forceinline__ void cpasync16(uint32_t dst, const void* src) {
    asm volatile("cp.async.cg.shared.global [%0], [%1], 16;"
                 :: "r"(dst), "l"(src));
}
#define CP_COMMIT() asm volatile("cp.async.commit_group;" ::: "memory")
#define CP_WAIT2()  asm volatile("cp.async.wait_group 2;" ::: "memory")
#define CP_WAIT1()  asm volatile("cp.async.wait_group 1;" ::: "memory")
#define CP_WAIT0()  asm volatile("cp.async.wait_group 0;" ::: "memory")

// ---------------------------------------------------------------- prep kernels
__global__ void conv_x_kernel(const float* __restrict__ x) {
    size_t idx = (size_t)blockIdx.x * blockDim.x + threadIdx.x;
    if (idx >= (size_t)NROWS * KDIM / 4) return;
    float4 v = ((const float4*)x)[idx];
    ushort4 hv = make_ushort4(__half_as_ushort(__float2half_rn(v.x)),
                              __half_as_ushort(__float2half_rn(v.y)),
                              __half_as_ushort(__float2half_rn(v.z)),
                              __half_as_ushort(__float2half_rn(v.w)));
    ((ushort4*)g_xf)[idx] = hv;
}

__global__ void conv_w1_kernel(const float* __restrict__ w) {
    int idx = blockIdx.x * blockDim.x + threadIdx.x;
    if (idx >= EQ * KDIM) return;
    int n = idx / KDIM;
    int k = idx - n * KDIM;
    g_w1f[idx] = __float2half_rn(w[(size_t)k * EQ + n]);
}

__global__ void conv_w2_kernel(const float* __restrict__ tw,
                               const float* __restrict__ tb,
                               const float* __restrict__ Tw,
                               const float* __restrict__ Tb) {
    int idx = blockIdx.x * blockDim.x + threadIdx.x;
    if (idx < N2P * KDIM) {
        int n = idx / KDIM;
        int k = idx - n * KDIM;
        float v = 0.0f;
        if (n < VQ)           v = tw[(size_t)k * VQ + n];
        else if (n < VQ + PQ) v = Tw[(size_t)k * PQ + (n - VQ)];
        g_w2f[idx] = __float2half_rn(v);
    }
    if (idx < N2P)
        g_b2[idx] = (idx < VQ) ? tb[idx] : (idx < VQ + PQ ? Tb[idx - VQ] : 0.0f);
}

// ---------------------------------------------------------------- GEMM (HMMA)
// C[128x128] = A @ B^T, fp16 operands, fp32 accumulate, K-major.
// 4-stage cp.async pipeline, KC=32, one __syncthreads per chunk, 2 CTAs/SM.
// FINE-GRAINED INTERLEAVE: each interleaved step issues the 6 LDSMs of the
// NEXT ks-step between the 16 MMAs of the CURRENT ks-step, so the smem and
// tensor pipes are fed alternately from every warp instead of in bursts.
template <bool GELU, typename OutT>
__global__ void __launch_bounds__(256, 2)
gemm_mma_kernel(const __half* __restrict__ Af,
                const __half* __restrict__ Bf,
                const float* __restrict__ bias, OutT* __restrict__ C,
                int ldc) {
    extern __shared__ char sm[];
    const uint32_t sb = smem_u32(sm);
    constexpr uint32_t RS = 80;
    constexpr uint32_t PIECE = 128 * RS;   // 10240
    constexpr uint32_t STAGE = 2 * PIECE;  // 20480

    int tid = threadIdx.x;
    int lane = tid & 31;
    int wid = tid >> 5;
    int wm = (wid & 3) * 32;
    int wn = (wid >> 2) * 64;
    int m0 = blockIdx.y * 128;
    int n0 = blockIdx.x * 128;

    // cp.async mapping
    int lr = tid >> 1;
    int c16 = (tid & 1) * 2;
    const __half* pA = Af + (size_t)(m0 + lr) * KDIM + c16 * 8;
    const __half* pB = Bf + (size_t)(n0 + lr) * KDIM + c16 * 8;
    uint32_t sOff = (uint32_t)lr * RS + (uint32_t)c16 * 16;

    auto issue = [&](int c) {
        uint32_t d = sb + (uint32_t)(c & (NSTG - 1)) * STAGE + sOff;
        size_t g = (size_t)c * KC;
        cpasync16(d,              pA + g);
        cpasync16(d + 16,         pA + g + 8);
        cpasync16(d + PIECE,      pB + g);
        cpasync16(d + PIECE + 16, pB + g + 8);
        CP_COMMIT();
    };

    // ldmatrix per-lane offsets
    int rA = (lane & 7) + ((lane >> 3) & 1) * 8;
    uint32_t kA = (uint32_t)((lane >> 4) & 1) * 16;
    int rB = (lane & 7) + ((lane >> 4) & 1) * 8;
    uint32_t kB = (uint32_t)((lane >> 3) & 1) * 16;

    float acc[2][8][4];
#pragma unroll
    for (int i = 0; i < 2; i++)
#pragma unroll
        for (int j = 0; j < 8; j++)
#pragma unroll
            for (int q = 0; q < 4; q++) acc[i][j][q] = 0.0f;

    uint32_t a0[2][4], b0[8][2];   // fragment ping
    uint32_t a1[2][4], b1[8][2];   // fragment pong

    // plain (non-interleaved) fragment load, for the prologue
    auto ldfrag = [&](uint32_t st, uint32_t kbyte, uint32_t (*ah)[4],
                      uint32_t (*bh)[2]) {
#pragma unroll
        for (int mf = 0; mf < 2; mf++)
            ldsm4(ah[mf], st + (uint32_t)(wm + mf * 16 + rA) * RS + kbyte + kA);
#pragma unroll
        for (int g = 0; g < 4; g++) {
            uint32_t t[4];
            ldsm4(t, st + PIECE +
                         (uint32_t)(wn + g * 16 + rB) * RS + kbyte + kB);
            bh[2 * g][0] = t[0]; bh[2 * g][1] = t[1];
            bh[2 * g + 1][0] = t[2]; bh[2 * g + 1][1] = t[3];
        }
    };

    // Interleaved step: MMA all 16 frag-products of (aC,bC) while loading
    // (aN,bN) from (stn, kbn). LDSMs are spread between MMA groups.
    auto istep = [&](uint32_t (&aC)[2][4], uint32_t (&bC)[8][2],
                     uint32_t (&aN)[2][4], uint32_t (&bN)[8][2],
                     uint32_t stn, uint32_t kbn) {
        ldsm4(aN[0], stn + (uint32_t)(wm + rA) * RS + kbn + kA);
        ldsm4(aN[1], stn + (uint32_t)(wm + 16 + rA) * RS + kbn + kA);
#pragma unroll
        for (int g = 0; g < 4; g++) {
            uint32_t t[4];
            ldsm4(t, stn + PIECE +
                         (uint32_t)(wn + g * 16 + rB) * RS + kbn + kB);
            mma16816(acc[0][2 * g],     aC[0], bC[2 * g]);
            mma16816(acc[1][2 * g],     aC[1], bC[2 * g]);
            mma16816(acc[0][2 * g + 1], aC[0], bC[2 * g + 1]);
            mma16816(acc[1][2 * g + 1], aC[1], bC[2 * g + 1]);
            bN[2 * g][0] = t[0]; bN[2 * g][1] = t[1];
            bN[2 * g + 1][0] = t[2]; bN[2 * g + 1][1] = t[3];
        }
    };

#define MMA_ALL(A, B)                                                         \
    _Pragma("unroll") for (int mf = 0; mf < 2; mf++)                          \
        _Pragma("unroll") for (int nf = 0; nf < 8; nf++)                      \
            mma16816(acc[mf][nf], (A)[mf], (B)[nf]);

    issue(0);
    issue(1);
    issue(2);
    CP_WAIT2();          // chunk 0 landed
    __syncthreads();
    ldfrag(sb, 0, a0, b0);

    for (int c = 0; c < NCH; c++) {
        uint32_t st = sb + (uint32_t)(c & (NSTG - 1)) * STAGE;
        // MMA ks0 of chunk c while loading ks1 fragments (interleaved)
        istep(a0, b0, a1, b1, st, 32);

        if (c + 1 < NCH) {
            // make chunk c+1 visible; retire readers of buffer (c+3)%4
            if (c + 2 < NCH) CP_WAIT1(); else CP_WAIT0();
            __syncthreads();
            if (c + 3 < NCH) issue(c + 3);
            // MMA ks1 of chunk c while loading ks0 of chunk c+1 (interleaved)
            istep(a1, b1, a0, b0,
                  sb + (uint32_t)((c + 1) & (NSTG - 1)) * STAGE, 0);
        } else {
            MMA_ALL(a1, b1);
        }
    }
#undef MMA_ALL

    // epilogue: bias (+ GELU); OutT = __half (GEMM1) or float (GEMM2)
    int tr = lane >> 2;
    int tc = (lane & 3) * 2;
#pragma unroll
    for (int mf = 0; mf < 2; mf++) {
#pragma unroll
        for (int nf = 0; nf < 8; nf++) {
            int col = n0 + wn + nf * 8 + tc;
            float2 bb = *(const float2*)&bias[col];
            int r1 = m0 + wm + mf * 16 + tr;
#pragma unroll
            for (int h = 0; h < 2; h++) {
                float v0 = acc[mf][nf][2 * h + 0] + bb.x;
                float v1 = acc[mf][nf][2 * h + 1] + bb.y;
                if (GELU) {
                    v0 = 0.5f * v0 * (1.0f + erff(v0 * 0.70710678118654752f));
                    v1 = 0.5f * v1 * (1.0f + erff(v1 * 0.70710678118654752f));
                }
                if constexpr (sizeof(OutT) == 2) {
                    __half2 hv = __floats2half2_rn(v0, v1);
                    *(__half2*)&C[(size_t)(r1 + 8 * h) * ldc + col] = hv;
                } else {
                    *(float2*)&C[(size_t)(r1 + 8 * h) * ldc + col] =
                        make_float2(v0, v1);
                }
            }
        }
    }
}

// ---------------------------------------------------------------- LayerNorm
__device__ __forceinline__ float block_reduce_sum(float v) {
    __shared__ float sh[8];
#pragma unroll
    for (int o = 16; o > 0; o >>= 1) v += __shfl_xor_sync(0xffffffffu, v, o);
    int lane = threadIdx.x & 31, wid = threadIdx.x >> 5;
    if (lane == 0) sh[wid] = v;
    __syncthreads();
    v = (lane < 8) ? sh[lane] : 0.0f;
#pragma unroll
    for (int o = 4; o > 0; o >>= 1) v += __shfl_xor_sync(0xffffffffu, v, o);
    v = __shfl_sync(0xffffffffu, v, 0);
    __syncthreads();
    return v;
}

// LN reads fp16 h, computes stats in fp32, writes fp16.
__global__ void ln_kernel(const __half* __restrict__ h,
                          const float* __restrict__ g,
                          const float* __restrict__ b) {
    size_t r = blockIdx.x;
    const __half* row = h + r * EQ;
    int t = threadIdx.x;
    float x[5];
    float s = 0.0f;
#pragma unroll
    for (int i = 0; i < 5; i++) {
        x[i] = __half2float(row[t + i * 256]);
        s += x[i];
    }
    float mu = block_reduce_sum(s) * (1.0f / EQ);
    float v = 0.0f;
#pragma unroll
    for (int i = 0; i < 5; i++) { float d = x[i] - mu; v += d * d; }
    float var = block_reduce_sum(v) * (1.0f / EQ);
    float inv = rsqrtf(var + LN_EPS);
#pragma unroll
    for (int i = 0; i < 5; i++) {
        int c = t + i * 256;
        float y = (x[i] - mu) * inv * g[c] + b[c];
        g_af[r * EQ + c] = __float2half_rn(y);
    }
}

// ---------------------------------------------------------------- finalize
__global__ void __launch_bounds__(256)
finalize_kernel(const int* __restrict__ mask32,
                float* __restrict__ qOut, float* __restrict__ piOut) {
    __shared__ float th[8][512];
    __shared__ float psq[8][32];
    __shared__ float mf[32];

    int lane = threadIdx.x;
    int w = threadIdx.y;
    size_t r = (size_t)blockIdx.x * 8 + w;

    if (w == 0) mf[lane] = (mask32[lane] != 0) ? 1.0f : 0.0f;
    __syncthreads();

    const float* base = g_l2 + r * N2P;

    bool mk = mf[lane] > 0.5f;
    float x = base[lane];
    float xm = mk ? x : -INFINITY;
    float mx = xm;
#pragma unroll
    for (int o = 16; o > 0; o >>= 1)
        mx = fmaxf(mx, __shfl_xor_sync(0xffffffffu, mx, o));
    float e = mk ? expf(xm - mx) : 0.0f;
    float ssum = e;
#pragma unroll
    for (int o = 16; o > 0; o >>= 1)
        ssum += __shfl_xor_sync(0xffffffffu, ssum, o);

    if (piOut) piOut[r * VQ + lane] = e / ssum;
    float logpi = xm - mx - logf(ssum);
    psq[w][lane] = mk ? expf(0.5f * logpi) : 1.0f;

    for (int idx = lane; idx < PQ; idx += 32) {
        float t = base[VQ + idx];
        th[w][idx] = fmaxf(t, 0.0f) + log1pf(expf(-fabsf(t)));
    }
    __syncwarp();

    int i = lane;
    float mi = mf[i];
    float inv = 1.0f / psq[w][i];
    float q[32];
    float rs = 0.0f;
#pragma unroll
    for (int j = 0; j < 32; j++) {
        float val = 0.0f;
        if (j != i) {
            int lo = min(i, j), hi = max(i, j);
            int idx = lo * VQ - (lo * (lo + 1)) / 2 + (hi - lo - 1);
            val = th[w][idx] * mi * mf[j] * psq[w][j] * inv;
        }
        q[j] = val;
        rs += val;
    }
#pragma unroll
    for (int j = 0; j < 32; j++)
        if (j == i) q[j] = -rs;

    float* out = qOut + r * (VQ * VQ) + (size_t)i * VQ;
#pragma unroll
    for (int j = 0; j < 32; j += 4)
        *(float4*)(out + j) = make_float4(q[j], q[j + 1], q[j + 2], q[j + 3]);
}

// ---------------------------------------------------------------- launch
extern "C" void kernel_launch(void* const* d_in, const int* in_sizes, int n_in,
                              void* d_out, int out_size) {
    const float* hx      = (const float*)d_in[0];
    const int*   vmask   = (const int*)d_in[1];
    const float* dense_w = (const float*)d_in[2];
    const float* dense_b = (const float*)d_in[3];
    const float* ln_g    = (const float*)d_in[4];
    const float* ln_b    = (const float*)d_in[5];
    const float* theta_w = (const float*)d_in[6];
    const float* theta_b = (const float*)d_in[7];
    const float* Theta_w = (const float*)d_in[8];
    const float* Theta_b = (const float*)d_in[9];

    float *l2ptr, *b2ptr;
    __half *hfp, *xf, *af, *w1f, *w2f;
    cudaGetSymbolAddress((void**)&hfp, g_hf);
    cudaGetSymbolAddress((void**)&l2ptr, g_l2);
    cudaGetSymbolAddress((void**)&b2ptr, g_b2);
    cudaGetSymbolAddress((void**)&xf, g_xf);
    cudaGetSymbolAddress((void**)&af, g_af);
    cudaGetSymbolAddress((void**)&w1f, g_w1f);
    cudaGetSymbolAddress((void**)&w2f, g_w2f);

    const size_t Q_ELEMS = (size_t)NROWS * VQ * VQ;
    const size_t PI_ELEMS = (size_t)NROWS * VQ;
    float* qOut = (float*)d_out;
    float* piOut = ((size_t)out_size >= Q_ELEMS + PI_ELEMS) ? (qOut + Q_ELEMS)
                                                            : nullptr;

    const int SMEM = NSTG * 2 * 128 * 80;   // 81920 bytes -> 2 CTAs/SM
    cudaFuncSetAttribute(gemm_mma_kernel<true, __half>,
                         cudaFuncAttributeMaxDynamicSharedMemorySize, SMEM);
    cudaFuncSetAttribute(gemm_mma_kernel<false, float>,
                         cudaFuncAttributeMaxDynamicSharedMemorySize, SMEM);

    // 1. prep: convert activations/weights to fp16 (weights K-major)
    conv_x_kernel<<<(NROWS * KDIM / 4 + 255) / 256, 256>>>(hx);
    conv_w1_kernel<<<(EQ * KDIM + 255) / 256, 256>>>(dense_w);
    conv_w2_kernel<<<(N2P * KDIM + 255) / 256, 256>>>(theta_w, theta_b,
                                                      Theta_w, Theta_b);

    // 2. h = gelu(hx @ dense_w + dense_b) -> fp16   [M=32768, N=1280, K=1280]
    {
        dim3 grid(EQ / 128, NROWS / 128);
        gemm_mma_kernel<true, __half><<<grid, 256, SMEM>>>(xf, w1f, dense_b,
                                                           hfp, EQ);
    }

    // 3. LayerNorm (fp16 in/out, fp32 stats)
    ln_kernel<<<NROWS, 256>>>(hfp, ln_g, ln_b);

    // 4. logits2 = LN(h) @ [theta|Theta] + bias  [M=32768, N=640, K=1280]
    {
        dim3 grid(N2P / 128, NROWS / 128);
        gemm_mma_kernel<false, float><<<grid, 256, SMEM>>>(af, w2f, b2ptr,
                                                           l2ptr, N2P);
    }

    // 5. per-row epilogue -> Q, pi
    finalize_kernel<<<NROWS / 8, dim3(32, 8)>>>(vmask, qOut, piOut);
}

// round 17
// speedup vs baseline: 1.3505x; 1.0265x over previous
#include <cuda_runtime.h>
#include <cuda_fp16.h>
#include <math.h>
#include <stdint.h>

// ---------------------------------------------------------------- constants
#define NROWS 32768          // B*L
#define EQ    1280
#define KDIM  1280
#define VQ    32
#define PQ    496
#define N2P   640            // padded width of second GEMM (528 -> 640)
#define LN_EPS 1e-12f
#define KC    32             // K per chunk (2 ks-steps of 16)
#define NCH   (KDIM / KC)    // 40
#define NSTG  4              // cp.async pipeline stages
#define KBLK  (KDIM / 16)    // 80 k-blocks of 16

// ---------------------------------------------------------------- scratch
__device__ __half g_hf[(size_t)NROWS * EQ];          // post-GELU hidden (fp16)
__device__ float g_l2[(size_t)NROWS * N2P];          // [pi_logits | Theta | pad]
__device__ __half g_xp[(size_t)NROWS * KDIM];        // hx fp16, FRAGMENT-MAJOR
__device__ __half g_af[(size_t)NROWS * KDIM];        // LN(h) fp16 (linear)
__device__ __half g_w1f[(size_t)EQ * KDIM];          // dense_w^T fp16 [n][k]
__device__ __half g_w2f[(size_t)N2P * KDIM];         // packed [theta|Theta]^T fp16
__device__ float g_b2[N2P];

// ---------------------------------------------------------------- PTX utils
__device__ __forceinline__ uint32_t smem_u32(const void* p) {
    uint32_t a;
    asm("{ .reg .u64 t; cvta.to.shared.u64 t, %1; cvt.u32.u64 %0, t; }"
        : "=r"(a) : "l"(p));
    return a;
}
__device__ __forceinline__ void ldsm4(uint32_t* r, uint32_t addr) {
    asm volatile("ldmatrix.sync.aligned.m8n8.x4.shared.b16 {%0,%1,%2,%3}, [%4];"
                 : "=r"(r[0]), "=r"(r[1]), "=r"(r[2]), "=r"(r[3]) : "r"(addr));
}
__device__ __forceinline__ void mma16816(float* d, const uint32_t* a,
                                         const uint32_t* b) {
    asm volatile(
        "mma.sync.aligned.m16n8k16.row.col.f32.f16.f16.f32 "
        "{%0,%1,%2,%3}, {%4,%5,%6,%7}, {%8,%9}, {%0,%1,%2,%3};"
        : "+f"(d[0]), "+f"(d[1]), "+f"(d[2]), "+f"(d[3])
        : "r"(a[0]), "r"(a[1]), "r"(a[2]), "r"(a[3]), "r"(b[0]), "r"(b[1]));
}
__device__ __forceinline__ void cpasync16(uint32_t dst, const void* src) {
    asm volatile("cp.async.cg.shared.global [%0], [%1], 16;"
                 :: "r"(dst), "l"(src));
}
#define CP_COMMIT() asm volatile("cp.async.commit_group;" ::: "memory")
#define CP_WAIT2()  asm volatile("cp.async.wait_group 2;" ::: "memory")
#define CP_WAIT1()  asm volatile("cp.async.wait_group 1;" ::: "memory")
#define CP_WAIT0()  asm volatile("cp.async.wait_group 0;" ::: "memory")

// ---------------------------------------------------------------- prep kernels
// conv_x: fp32 -> fp16, PERMUTED into m16n8k16 A-fragment-major 16x16 blocks.
// Each thread emits one lane-line (16B = 8 halfs) of one block:
//   reg0 = (r, c0..c0+1)   reg1 = (r+8, c0..c0+1)
//   reg2 = (r, c0+8..+9)   reg3 = (r+8, c0+8..+9)
// with r = lane>>2, c0 = (lane&3)*2.
__global__ void conv_x_perm_kernel(const float* __restrict__ x) {
    size_t chunk = (size_t)blockIdx.x * blockDim.x + threadIdx.x;
    if (chunk >= (size_t)NROWS * KDIM / 8) return;
    int lane = (int)(chunk & 31);
    size_t blk = chunk >> 5;
    int bk = (int)(blk % KBLK);
    size_t bm = blk / KBLK;
    int r = lane >> 2;
    int c0 = (lane & 3) * 2;
    const float* base = x + (bm * 16) * (size_t)KDIM + bk * 16;
    float2 v0 = *(const float2*)(base + (size_t)r * KDIM + c0);
    float2 v1 = *(const float2*)(base + (size_t)(r + 8) * KDIM + c0);
    float2 v2 = *(const float2*)(base + (size_t)r * KDIM + c0 + 8);
    float2 v3 = *(const float2*)(base + (size_t)(r + 8) * KDIM + c0 + 8);
    __half2 h0 = __floats2half2_rn(v0.x, v0.y);
    __half2 h1 = __floats2half2_rn(v1.x, v1.y);
    __half2 h2 = __floats2half2_rn(v2.x, v2.y);
    __half2 h3 = __floats2half2_rn(v3.x, v3.y);
    uint4 out = make_uint4(*(uint32_t*)&h0, *(uint32_t*)&h1,
                           *(uint32_t*)&h2, *(uint32_t*)&h3);
    ((uint4*)g_xp)[chunk] = out;
}

__global__ void conv_w1_kernel(const float* __restrict__ w) {
    int idx = blockIdx.x * blockDim.x + threadIdx.x;
    if (idx >= EQ * KDIM) return;
    int n = idx / KDIM;
    int k = idx - n * KDIM;
    g_w1f[idx] = __float2half_rn(w[(size_t)k * EQ + n]);
}

__global__ void conv_w2_kernel(const float* __restrict__ tw,
                               const float* __restrict__ tb,
                               const float* __restrict__ Tw,
                               const float* __restrict__ Tb) {
    int idx = blockIdx.x * blockDim.x + threadIdx.x;
    if (idx < N2P * KDIM) {
        int n = idx / KDIM;
        int k = idx - n * KDIM;
        float v = 0.0f;
        if (n < VQ)           v = tw[(size_t)k * VQ + n];
        else if (n < VQ + PQ) v = Tw[(size_t)k * PQ + (n - VQ)];
        g_w2f[idx] = __float2half_rn(v);
    }
    if (idx < N2P)
        g_b2[idx] = (idx < VQ) ? tb[idx] : (idx < VQ + PQ ? Tb[idx - VQ] : 0.0f);
}

// ---------------------------------------------------------------- GEMM1
// C[128x128] = A @ B^T, A fp16 fragment-major in GLOBAL (direct LDG.128 per
// fragment, no smem round-trip), B fp16 K-major via cp.async+ldsm. GELU
// epilogue, fp16 output. SMEM per stage: B only, 128x80B = 10240B. 2 CTAs/SM.
// One 16x16 block = 256 halfs = 32 uint4; block (bm,bk) at uint4 offset
// (bm*KBLK + bk)*32 + lane.
__global__ void __launch_bounds__(256, 2)
gemm1_kernel(const __half* __restrict__ Ap,
             const __half* __restrict__ Bf,
             const float* __restrict__ bias, __half* __restrict__ C,
             int ldc) {
    extern __shared__ char sm[];
    const uint32_t sb = smem_u32(sm);
    constexpr uint32_t RS = 80;
    constexpr uint32_t STAGE = 128 * RS;   // 10240 (B only)

    int tid = threadIdx.x;
    int lane = tid & 31;
    int wid = tid >> 5;
    int wm = (wid & 3) * 32;
    int wn = (wid >> 2) * 64;
    int m0 = blockIdx.y * 128;
    int n0 = blockIdx.x * 128;

    // A fragment-major pointers: block row bm = (m0+wm)/16 (+mf)
    const uint4* pA0 = (const uint4*)Ap +
        (size_t)((m0 + wm) >> 4) * KBLK * 32 + lane;
    const uint4* pA1 = pA0 + (size_t)KBLK * 32;    // +1 block row (16 m-rows)

    // cp.async mapping for B: thread -> (row = tid>>1, one 16B half)
    int lr = tid >> 1;
    int c16 = (tid & 1) * 2;
    const __half* pB = Bf + (size_t)(n0 + lr) * KDIM + c16 * 8;
    uint32_t sOff = (uint32_t)lr * RS + (uint32_t)c16 * 16;

    auto issue = [&](int c) {
        uint32_t d = sb + (uint32_t)(c & (NSTG - 1)) * STAGE + sOff;
        size_t g = (size_t)c * KC;
        cpasync16(d,      pB + g);
        cpasync16(d + 16, pB + g + 8);
        CP_COMMIT();
    };

    // A fragment LDG: k-block index kb (0..79); fills a[2][4]
    auto ldgA = [&](int kb, uint32_t (*a)[4]) {
        uint4 v0 = pA0[(size_t)kb * 32];
        uint4 v1 = pA1[(size_t)kb * 32];
        a[0][0] = v0.x; a[0][1] = v0.y; a[0][2] = v0.z; a[0][3] = v0.w;
        a[1][0] = v1.x; a[1][1] = v1.y; a[1][2] = v1.z; a[1][3] = v1.w;
    };

    // ldmatrix per-lane offsets (B)
    int rB = (lane & 7) + ((lane >> 4) & 1) * 8;
    uint32_t kB = (uint32_t)((lane >> 3) & 1) * 16;

    float acc[2][8][4];
#pragma unroll
    for (int i = 0; i < 2; i++)
#pragma unroll
        for (int j = 0; j < 8; j++)
#pragma unroll
            for (int q = 0; q < 4; q++) acc[i][j][q] = 0.0f;

    uint32_t a0[2][4], a1[2][4];
    uint32_t b0[8][2], b1[8][2];

    // plain B fragment load (prologue)
    auto ldfragB = [&](uint32_t st, uint32_t kbyte, uint32_t (*bh)[2]) {
#pragma unroll
        for (int g = 0; g < 4; g++) {
            uint32_t t[4];
            ldsm4(t, st + (uint32_t)(wn + g * 16 + rB) * RS + kbyte + kB);
            bh[2 * g][0] = t[0]; bh[2 * g][1] = t[1];
            bh[2 * g + 1][0] = t[2]; bh[2 * g + 1][1] = t[3];
        }
    };

    // interleaved step: MMA(aC,bC) while loading bN via ldsm
    auto istep = [&](uint32_t (&aC)[2][4], uint32_t (&bC)[8][2],
                     uint32_t (&bN)[8][2], uint32_t stn, uint32_t kbn) {
#pragma unroll
        for (int g = 0; g < 4; g++) {
            uint32_t t[4];
            ldsm4(t, stn + (uint32_t)(wn + g * 16 + rB) * RS + kbn + kB);
            mma16816(acc[0][2 * g],     aC[0], bC[2 * g]);
            mma16816(acc[1][2 * g],     aC[1], bC[2 * g]);
            mma16816(acc[0][2 * g + 1], aC[0], bC[2 * g + 1]);
            mma16816(acc[1][2 * g + 1], aC[1], bC[2 * g + 1]);
            bN[2 * g][0] = t[0]; bN[2 * g][1] = t[1];
            bN[2 * g + 1][0] = t[2]; bN[2 * g + 1][1] = t[3];
        }
    };

#define MMA_ALL(A, B)                                                         \
    _Pragma("unroll") for (int mf = 0; mf < 2; mf++)                          \
        _Pragma("unroll") for (int nf = 0; nf < 8; nf++)                      \
            mma16816(acc[mf][nf], (A)[mf], (B)[nf]);

    issue(0);
    issue(1);
    issue(2);
    ldgA(0, a0);         // A ks0 of chunk 0 (independent of smem pipeline)
    CP_WAIT2();          // B chunk 0 landed
    __syncthreads();
    ldfragB(sb, 0, b0);

    for (int c = 0; c < NCH; c++) {
        uint32_t st = sb + (uint32_t)(c & (NSTG - 1)) * STAGE;
        ldgA(2 * c + 1, a1);                 // A ks1 of chunk c
        istep(a0, b0, b1, st, 32);           // MMA ks0, load B ks1

        if (c + 1 < NCH) {
            if (c + 2 < NCH) CP_WAIT1(); else CP_WAIT0();
            __syncthreads();
            if (c + 3 < NCH) issue(c + 3);
            ldgA(2 * (c + 1), a0);           // A ks0 of chunk c+1
            istep(a1, b1, b0,
                  sb + (uint32_t)((c + 1) & (NSTG - 1)) * STAGE, 0);
        } else {
            MMA_ALL(a1, b1);
        }
    }
#undef MMA_ALL

    // epilogue: bias + exact GELU, fp16 stores
    int tr = lane >> 2;
    int tc = (lane & 3) * 2;
#pragma unroll
    for (int mf = 0; mf < 2; mf++) {
#pragma unroll
        for (int nf = 0; nf < 8; nf++) {
            int col = n0 + wn + nf * 8 + tc;
            float2 bb = *(const float2*)&bias[col];
            int r1 = m0 + wm + mf * 16 + tr;
#pragma unroll
            for (int h = 0; h < 2; h++) {
                float v0 = acc[mf][nf][2 * h + 0] + bb.x;
                float v1 = acc[mf][nf][2 * h + 1] + bb.y;
                v0 = 0.5f * v0 * (1.0f + erff(v0 * 0.70710678118654752f));
                v1 = 0.5f * v1 * (1.0f + erff(v1 * 0.70710678118654752f));
                __half2 hv = __floats2half2_rn(v0, v1);
                *(__half2*)&C[(size_t)(r1 + 8 * h) * ldc + col] = hv;
            }
        }
    }
}

// ---------------------------------------------------------------- GEMM2 (R15)
template <bool GELU, typename OutT>
__global__ void __launch_bounds__(256, 2)
gemm_mma_kernel(const __half* __restrict__ Af,
                const __half* __restrict__ Bf,
                const float* __restrict__ bias, OutT* __restrict__ C,
                int ldc) {
    extern __shared__ char sm[];
    const uint32_t sb = smem_u32(sm);
    constexpr uint32_t RS = 80;
    constexpr uint32_t PIECE = 128 * RS;   // 10240
    constexpr uint32_t STAGE = 2 * PIECE;  // 20480

    int tid = threadIdx.x;
    int lane = tid & 31;
    int wid = tid >> 5;
    int wm = (wid & 3) * 32;
    int wn = (wid >> 2) * 64;
    int m0 = blockIdx.y * 128;
    int n0 = blockIdx.x * 128;

    int lr = tid >> 1;
    int c16 = (tid & 1) * 2;
    const __half* pA = Af + (size_t)(m0 + lr) * KDIM + c16 * 8;
    const __half* pB = Bf + (size_t)(n0 + lr) * KDIM + c16 * 8;
    uint32_t sOff = (uint32_t)lr * RS + (uint32_t)c16 * 16;

    auto issue = [&](int c) {
        uint32_t d = sb + (uint32_t)(c & (NSTG - 1)) * STAGE + sOff;
        size_t g = (size_t)c * KC;
        cpasync16(d,              pA + g);
        cpasync16(d + 16,         pA + g + 8);
        cpasync16(d + PIECE,      pB + g);
        cpasync16(d + PIECE + 16, pB + g + 8);
        CP_COMMIT();
    };

    int rA = (lane & 7) + ((lane >> 3) & 1) * 8;
    uint32_t kA = (uint32_t)((lane >> 4) & 1) * 16;
    int rB = (lane & 7) + ((lane >> 4) & 1) * 8;
    uint32_t kB = (uint32_t)((lane >> 3) & 1) * 16;

    float acc[2][8][4];
#pragma unroll
    for (int i = 0; i < 2; i++)
#pragma unroll
        for (int j = 0; j < 8; j++)
#pragma unroll
            for (int q = 0; q < 4; q++) acc[i][j][q] = 0.0f;

    uint32_t a0[2][4], b0[8][2];
    uint32_t a1[2][4], b1[8][2];

    auto ldfrag = [&](uint32_t st, uint32_t kbyte, uint32_t (*ah)[4],
                      uint32_t (*bh)[2]) {
#pragma unroll
        for (int mf = 0; mf < 2; mf++)
            ldsm4(ah[mf], st + (uint32_t)(wm + mf * 16 + rA) * RS + kbyte + kA);
#pragma unroll
        for (int g = 0; g < 4; g++) {
            uint32_t t[4];
            ldsm4(t, st + PIECE +
                         (uint32_t)(wn + g * 16 + rB) * RS + kbyte + kB);
            bh[2 * g][0] = t[0]; bh[2 * g][1] = t[1];
            bh[2 * g + 1][0] = t[2]; bh[2 * g + 1][1] = t[3];
        }
    };

    auto istep = [&](uint32_t (&aC)[2][4], uint32_t (&bC)[8][2],
                     uint32_t (&aN)[2][4], uint32_t (&bN)[8][2],
                     uint32_t stn, uint32_t kbn) {
        ldsm4(aN[0], stn + (uint32_t)(wm + rA) * RS + kbn + kA);
        ldsm4(aN[1], stn + (uint32_t)(wm + 16 + rA) * RS + kbn + kA);
#pragma unroll
        for (int g = 0; g < 4; g++) {
            uint32_t t[4];
            ldsm4(t, stn + PIECE +
                         (uint32_t)(wn + g * 16 + rB) * RS + kbn + kB);
            mma16816(acc[0][2 * g],     aC[0], bC[2 * g]);
            mma16816(acc[1][2 * g],     aC[1], bC[2 * g]);
            mma16816(acc[0][2 * g + 1], aC[0], bC[2 * g + 1]);
            mma16816(acc[1][2 * g + 1], aC[1], bC[2 * g + 1]);
            bN[2 * g][0] = t[0]; bN[2 * g][1] = t[1];
            bN[2 * g + 1][0] = t[2]; bN[2 * g + 1][1] = t[3];
        }
    };

#define MMA_ALL(A, B)                                                         \
    _Pragma("unroll") for (int mf = 0; mf < 2; mf++)                          \
        _Pragma("unroll") for (int nf = 0; nf < 8; nf++)                      \
            mma16816(acc[mf][nf], (A)[mf], (B)[nf]);

    issue(0);
    issue(1);
    issue(2);
    CP_WAIT2();
    __syncthreads();
    ldfrag(sb, 0, a0, b0);

    for (int c = 0; c < NCH; c++) {
        uint32_t st = sb + (uint32_t)(c & (NSTG - 1)) * STAGE;
        istep(a0, b0, a1, b1, st, 32);
        if (c + 1 < NCH) {
            if (c + 2 < NCH) CP_WAIT1(); else CP_WAIT0();
            __syncthreads();
            if (c + 3 < NCH) issue(c + 3);
            istep(a1, b1, a0, b0,
                  sb + (uint32_t)((c + 1) & (NSTG - 1)) * STAGE, 0);
        } else {
            MMA_ALL(a1, b1);
        }
    }
#undef MMA_ALL

    int tr = lane >> 2;
    int tc = (lane & 3) * 2;
#pragma unroll
    for (int mf = 0; mf < 2; mf++) {
#pragma unroll
        for (int nf = 0; nf < 8; nf++) {
            int col = n0 + wn + nf * 8 + tc;
            float2 bb = *(const float2*)&bias[col];
            int r1 = m0 + wm + mf * 16 + tr;
#pragma unroll
            for (int h = 0; h < 2; h++) {
                float v0 = acc[mf][nf][2 * h + 0] + bb.x;
                float v1 = acc[mf][nf][2 * h + 1] + bb.y;
                if (GELU) {
                    v0 = 0.5f * v0 * (1.0f + erff(v0 * 0.70710678118654752f));
                    v1 = 0.5f * v1 * (1.0f + erff(v1 * 0.70710678118654752f));
                }
                if constexpr (sizeof(OutT) == 2) {
                    __half2 hv = __floats2half2_rn(v0, v1);
                    *(__half2*)&C[(size_t)(r1 + 8 * h) * ldc + col] = hv;
                } else {
                    *(float2*)&C[(size_t)(r1 + 8 * h) * ldc + col] =
                        make_float2(v0, v1);
                }
            }
        }
    }
}

// ---------------------------------------------------------------- LayerNorm
__device__ __forceinline__ float block_reduce_sum(float v) {
    __shared__ float sh[8];
#pragma unroll
    for (int o = 16; o > 0; o >>= 1) v += __shfl_xor_sync(0xffffffffu, v, o);
    int lane = threadIdx.x & 31, wid = threadIdx.x >> 5;
    if (lane == 0) sh[wid] = v;
    __syncthreads();
    v = (lane < 8) ? sh[lane] : 0.0f;
#pragma unroll
    for (int o = 4; o > 0; o >>= 1) v += __shfl_xor_sync(0xffffffffu, v, o);
    v = __shfl_sync(0xffffffffu, v, 0);
    __syncthreads();
    return v;
}

__global__ void ln_kernel(const __half* __restrict__ h,
                          const float* __restrict__ g,
                          const float* __restrict__ b) {
    size_t r = blockIdx.x;
    const __half* row = h + r * EQ;
    int t = threadIdx.x;
    float x[5];
    float s = 0.0f;
#pragma unroll
    for (int i = 0; i < 5; i++) {
        x[i] = __half2float(row[t + i * 256]);
        s += x[i];
    }
    float mu = block_reduce_sum(s) * (1.0f / EQ);
    float v = 0.0f;
#pragma unroll
    for (int i = 0; i < 5; i++) { float d = x[i] - mu; v += d * d; }
    float var = block_reduce_sum(v) * (1.0f / EQ);
    float inv = rsqrtf(var + LN_EPS);
#pragma unroll
    for (int i = 0; i < 5; i++) {
        int c = t + i * 256;
        float y = (x[i] - mu) * inv * g[c] + b[c];
        g_af[r * EQ + c] = __float2half_rn(y);
    }
}

// ---------------------------------------------------------------- finalize
__global__ void __launch_bounds__(256)
finalize_kernel(const int* __restrict__ mask32,
                float* __restrict__ qOut, float* __restrict__ piOut) {
    __shared__ float th[8][512];
    __shared__ float psq[8][32];
    __shared__ float mf[32];

    int lane = threadIdx.x;
    int w = threadIdx.y;
    size_t r = (size_t)blockIdx.x * 8 + w;

    if (w == 0) mf[lane] = (mask32[lane] != 0) ? 1.0f : 0.0f;
    __syncthreads();

    const float* base = g_l2 + r * N2P;

    bool mk = mf[lane] > 0.5f;
    float x = base[lane];
    float xm = mk ? x : -INFINITY;
    float mx = xm;
#pragma unroll
    for (int o = 16; o > 0; o >>= 1)
        mx = fmaxf(mx, __shfl_xor_sync(0xffffffffu, mx, o));
    float e = mk ? expf(xm - mx) : 0.0f;
    float ssum = e;
#pragma unroll
    for (int o = 16; o > 0; o >>= 1)
        ssum += __shfl_xor_sync(0xffffffffu, ssum, o);

    if (piOut) piOut[r * VQ + lane] = e / ssum;
    float logpi = xm - mx - logf(ssum);
    psq[w][lane] = mk ? expf(0.5f * logpi) : 1.0f;

    for (int idx = lane; idx < PQ; idx += 32) {
        float t = base[VQ + idx];
        th[w][idx] = fmaxf(t, 0.0f) + log1pf(expf(-fabsf(t)));
    }
    __syncwarp();

    int i = lane;
    float mi = mf[i];
    float inv = 1.0f / psq[w][i];
    float q[32];
    float rs = 0.0f;
#pragma unroll
    for (int j = 0; j < 32; j++) {
        float val = 0.0f;
        if (j != i) {
            int lo = min(i, j), hi = max(i, j);
            int idx = lo * VQ - (lo * (lo + 1)) / 2 + (hi - lo - 1);
            val = th[w][idx] * mi * mf[j] * psq[w][j] * inv;
        }
        q[j] = val;
        rs += val;
    }
#pragma unroll
    for (int j = 0; j < 32; j++)
        if (j == i) q[j] = -rs;

    float* out = qOut + r * (VQ * VQ) + (size_t)i * VQ;
#pragma unroll
    for (int j = 0; j < 32; j += 4)
        *(float4*)(out + j) = make_float4(q[j], q[j + 1], q[j + 2], q[j + 3]);
}

// ---------------------------------------------------------------- launch
extern "C" void kernel_launch(void* const* d_in, const int* in_sizes, int n_in,
                              void* d_out, int out_size) {
    const float* hx      = (const float*)d_in[0];
    const int*   vmask   = (const int*)d_in[1];
    const float* dense_w = (const float*)d_in[2];
    const float* dense_b = (const float*)d_in[3];
    const float* ln_g    = (const float*)d_in[4];
    const float* ln_b    = (const float*)d_in[5];
    const float* theta_w = (const float*)d_in[6];
    const float* theta_b = (const float*)d_in[7];
    const float* Theta_w = (const float*)d_in[8];
    const float* Theta_b = (const float*)d_in[9];

    float *l2ptr, *b2ptr;
    __half *hfp, *xp, *af, *w1f, *w2f;
    cudaGetSymbolAddress((void**)&hfp, g_hf);
    cudaGetSymbolAddress((void**)&l2ptr, g_l2);
    cudaGetSymbolAddress((void**)&b2ptr, g_b2);
    cudaGetSymbolAddress((void**)&xp, g_xp);
    cudaGetSymbolAddress((void**)&af, g_af);
    cudaGetSymbolAddress((void**)&w1f, g_w1f);
    cudaGetSymbolAddress((void**)&w2f, g_w2f);

    const size_t Q_ELEMS = (size_t)NROWS * VQ * VQ;
    const size_t PI_ELEMS = (size_t)NROWS * VQ;
    float* qOut = (float*)d_out;
    float* piOut = ((size_t)out_size >= Q_ELEMS + PI_ELEMS) ? (qOut + Q_ELEMS)
                                                            : nullptr;

    const int SMEM1 = NSTG * 128 * 80;       // 40960 (B only)
    const int SMEM2 = NSTG * 2 * 128 * 80;   // 81920
    cudaFuncSetAttribute(gemm1_kernel,
                         cudaFuncAttributeMaxDynamicSharedMemorySize, SMEM1);
    cudaFuncSetAttribute(gemm_mma_kernel<false, float>,
                         cudaFuncAttributeMaxDynamicSharedMemorySize, SMEM2);

    // 1. prep
    {
        size_t chunks = (size_t)NROWS * KDIM / 8;
        conv_x_perm_kernel<<<(int)((chunks + 255) / 256), 256>>>(hx);
    }
    conv_w1_kernel<<<(EQ * KDIM + 255) / 256, 256>>>(dense_w);
    conv_w2_kernel<<<(N2P * KDIM + 255) / 256, 256>>>(theta_w, theta_b,
                                                      Theta_w, Theta_b);

    // 2. h = gelu(hx @ dense_w + dense_b) -> fp16 (A direct-LDG)
    {
        dim3 grid(EQ / 128, NROWS / 128);
        gemm1_kernel<<<grid, 256, SMEM1>>>(xp, w1f, dense_b, hfp, EQ);
    }

    // 3. LayerNorm (fp16 in/out, fp32 stats)
    ln_kernel<<<NROWS, 256>>>(hfp, ln_g, ln_b);

    // 4. logits2 = LN(h) @ [theta|Theta] + bias
    {
        dim3 grid(N2P / 128, NROWS / 128);
        gemm_mma_kernel<false, float><<<grid, 256, SMEM2>>>(af, w2f, b2ptr,
                                                            l2ptr, N2P);
    }

    // 5. per-row epilogue -> Q, pi
    finalize_kernel<<<NROWS / 8, dim3(32, 8)>>>(vmask, qOut, piOut);
}